// round 16
// baseline (speedup 1.0000x reference)
#include <cuda_runtime.h>
#include <cstdint>

// out[b, :] = table_bits[idx(b), :],  idx(b) = sum_k idx_bits[b,k] << (5-k)
// Table packed once into 64-bit masks (build kernel). Main kernel: each block
// expands 64 rows (16 KB) into smem (STS.128, conflict-free), then ONE
// cp.async.bulk shared->global drains the tile, bypassing the LSU/STG path.

#define BATCH   262144
#define THREADS 256
#define ROWS_PER_BLOCK 64
#define GRID (BATCH / ROWS_PER_BLOCK)      // 4096 blocks, 16KB output each

// Mask for table row r: column c (0..63) lives at bit (63 - c).
__device__ unsigned long long g_masks[64];

__global__ void build_masks_kernel(const float* __restrict__ table)
{
    int w    = (blockIdx.x * blockDim.x + threadIdx.x) >> 5;   // 0..63 table row
    int lane = threadIdx.x & 31;
    float v0 = table[w * 64 + lane];        // cols 0..31
    float v1 = table[w * 64 + 32 + lane];   // cols 32..63
    unsigned hi = __brev(__ballot_sync(0xFFFFFFFFu, v0 > 0.5f)); // col c -> bit 31-c
    unsigned lo = __brev(__ballot_sync(0xFFFFFFFFu, v1 > 0.5f));
    if (lane == 0)
        g_masks[w] = ((unsigned long long)hi << 32) | (unsigned long long)lo;
}

__device__ __forceinline__ float bit_to_1f(unsigned nib, int k)
{
    // nibble bit (3-k) -> 0.0f / 1.0f  (1.0f = 0x3F800000)
    return __int_as_float(((int)(nib << (28 + k)) >> 31) & 0x3F800000);
}

__global__ __launch_bounds__(THREADS)
void spike_lookup_kernel(const int* __restrict__ bits,    // BATCH*6
                         float*     __restrict__ out)     // BATCH*64
{
    __shared__ float4 buf[ROWS_PER_BLOCK * 16];   // 16 KB tile

    const int lane = threadIdx.x & 31;
    const int warp = threadIdx.x >> 5;            // 0..7, 8 rows each

    // ---- 8 rows * 6 ints = 48 ints per warp, coalesced ----
    const int* __restrict__ p = bits + blockIdx.x * (ROWS_PER_BLOCK * 6) + warp * 48;
    int v0 = p[lane];
    int v1 = (lane < 16) ? p[lane + 32] : 0;

    unsigned b0 = __ballot_sync(0xFFFFFFFFu, v0 != 0);  // int m -> bit m
    unsigned b1 = __ballot_sync(0xFFFFFFFFu, v1 != 0);
    unsigned long long u = (unsigned long long)b0 | ((unsigned long long)b1 << 32);

    const int j    = lane & 15;        // float4 column within the 64-float row
    const int half = lane >> 4;        // row parity within the pair
    const int s    = 60 - 4 * j;       // cols 4j..4j+3 -> nibble bits 3..0
    const int hb   = 6 * half;

    float4* __restrict__ dst = buf + warp * 128 + lane;

    #pragma unroll
    for (int i = 0; i < 4; i++) {
        int sh = 12 * i + hb;                          // row r = 2i+half
        unsigned vb = (unsigned)(u >> sh) & 63u;
        int idx = (int)(__brev(vb) >> 26);             // k=0 is MSB (weight 32)

        unsigned long long m = __ldg(&g_masks[idx]);   // L1-hot broadcast
        unsigned nib = (unsigned)(m >> s) & 0xFu;

        float4 v;
        v.x = bit_to_1f(nib, 0);
        v.y = bit_to_1f(nib, 1);
        v.z = bit_to_1f(nib, 2);
        v.w = bit_to_1f(nib, 3);
        dst[i * 32] = v;                               // conflict-free STS.128
    }

    __syncthreads();
    // Order generic STS before async-proxy TMA read of smem.
    asm volatile("fence.proxy.async.shared::cta;" ::: "memory");

    if (threadIdx.x == 0) {
        float* g = out + (size_t)blockIdx.x * (ROWS_PER_BLOCK * 64);
        unsigned saddr = (unsigned)__cvta_generic_to_shared(buf);
        asm volatile("cp.async.bulk.global.shared::cta.bulk_group [%0], [%1], %2;"
                     :: "l"(g), "r"(saddr), "r"(16384) : "memory");
        asm volatile("cp.async.bulk.commit_group;" ::: "memory");
        asm volatile("cp.async.bulk.wait_group 0;" ::: "memory");
    }
}

extern "C" void kernel_launch(void* const* d_in, const int* in_sizes, int n_in,
                              void* d_out, int out_size)
{
    const float* table = (const float*)d_in[0];
    const int*   bits  = (const int*)d_in[1];
    float*       out   = (float*)d_out;

    build_masks_kernel<<<2, 1024>>>(table);           // 64 warps, one per row
    spike_lookup_kernel<<<GRID, THREADS>>>(bits, out);
}

// round 17
// speedup vs baseline: 1.1509x; 1.1509x over previous
#include <cuda_runtime.h>

// out[b, :] = table_bits[idx(b), :],  idx(b) = sum_k idx_bits[b,k] << (5-k)
// Table values are 0/1 pulses -> packed once into 64-bit masks (build kernel).
// Main kernel = R7 champion + pinned occupancy + pipelined mask loads:
// all 8 indices (ALU) -> load m0..3 -> load m4..7 overlapped with stores 0..3.

#define BATCH   262144
#define THREADS 256
#define ROWS_PER_WARP 16
#define GRID (BATCH / (ROWS_PER_WARP * (THREADS / 32)))   // 2048 blocks

// Mask for table row r: column c (0..63) lives at bit (63 - c).
__device__ unsigned long long g_masks[64];

__global__ void build_masks_kernel(const float* __restrict__ table)
{
    int w    = (blockIdx.x * blockDim.x + threadIdx.x) >> 5;   // 0..63 table row
    int lane = threadIdx.x & 31;
    float v0 = table[w * 64 + lane];        // cols 0..31
    float v1 = table[w * 64 + 32 + lane];   // cols 32..63
    unsigned hi = __brev(__ballot_sync(0xFFFFFFFFu, v0 > 0.5f)); // col c -> bit 31-c
    unsigned lo = __brev(__ballot_sync(0xFFFFFFFFu, v1 > 0.5f));
    if (lane == 0)
        g_masks[w] = ((unsigned long long)hi << 32) | (unsigned long long)lo;
}

__device__ __forceinline__ float bit_to_1f(unsigned nib, int k)
{
    // nibble bit (3-k) -> 0.0f / 1.0f  (1.0f = 0x3F800000)
    return __int_as_float(((int)(nib << (28 + k)) >> 31) & 0x3F800000);
}

__global__ __launch_bounds__(THREADS, 8)
void spike_lookup_kernel(const int* __restrict__ bits,    // BATCH*6
                         float4*    __restrict__ out4)    // BATCH*16
{
    const int lane  = threadIdx.x & 31;
    const int gwarp = blockIdx.x * (THREADS / 32) + (threadIdx.x >> 5);

    // 16 rows * 6 ints = 96 ints, fully coalesced.
    const int* __restrict__ p = bits + gwarp * 96;
    unsigned b0 = __ballot_sync(0xFFFFFFFFu, p[lane]      != 0); // int m -> bit m
    unsigned b1 = __ballot_sync(0xFFFFFFFFu, p[lane + 32] != 0);
    unsigned b2 = __ballot_sync(0xFFFFFFFFu, p[lane + 64] != 0);

    unsigned long long u01 = (unsigned long long)b0 | ((unsigned long long)b1 << 32);
    unsigned long long u12 = (unsigned long long)b1 | ((unsigned long long)b2 << 32);

    const int j    = lane & 15;        // float4 column within the 64-float row
    const int half = lane >> 4;        // row parity within the pair
    const int s    = 60 - 4 * j;       // cols 4j..4j+3 -> nibble bits 3..0

    // ---- All 8 indices up front (pure ALU) ----
    int idxv[8];
    #pragma unroll
    for (int i = 0; i < 8; i++) {
        int r  = 2 * i + half;                    // local row 0..15
        int sh = 6 * r;
        unsigned vb = (r < 10) ? (unsigned)(u01 >> sh)
                               : (unsigned)(u12 >> (sh - 32));
        idxv[i] = (int)(__brev(vb & 63u) >> 26);  // k=0 is MSB (weight 32)
    }

    float4* __restrict__ dst = out4 + (long long)gwarp * 256 + lane;

    // ---- Pipelined: load group 0 masks ----
    unsigned long long m0[4];
    #pragma unroll
    for (int i = 0; i < 4; i++)
        m0[i] = __ldg(&g_masks[idxv[i]]);

    // ---- Load group 1 masks (overlaps group-0 expand/stores below) ----
    unsigned long long m1[4];
    #pragma unroll
    for (int i = 0; i < 4; i++)
        m1[i] = __ldg(&g_masks[idxv[4 + i]]);

    // ---- Expand + store group 0 ----
    #pragma unroll
    for (int i = 0; i < 4; i++) {
        unsigned nib = (unsigned)(m0[i] >> s) & 0xFu;
        float4 v;
        v.x = bit_to_1f(nib, 0);
        v.y = bit_to_1f(nib, 1);
        v.z = bit_to_1f(nib, 2);
        v.w = bit_to_1f(nib, 3);
        dst[i * 32] = v;                          // 512B contiguous per warp
    }

    // ---- Expand + store group 1 ----
    #pragma unroll
    for (int i = 0; i < 4; i++) {
        unsigned nib = (unsigned)(m1[i] >> s) & 0xFu;
        float4 v;
        v.x = bit_to_1f(nib, 0);
        v.y = bit_to_1f(nib, 1);
        v.z = bit_to_1f(nib, 2);
        v.w = bit_to_1f(nib, 3);
        dst[(4 + i) * 32] = v;
    }
}

extern "C" void kernel_launch(void* const* d_in, const int* in_sizes, int n_in,
                              void* d_out, int out_size)
{
    const float* table = (const float*)d_in[0];
    const int*   bits  = (const int*)d_in[1];
    float4*      out4  = (float4*)d_out;

    build_masks_kernel<<<2, 1024>>>(table);           // 64 warps, one per row
    spike_lookup_kernel<<<GRID, THREADS>>>(bits, out4);
}